// round 15
// baseline (speedup 1.0000x reference)
#include <cuda_runtime.h>
#include <cuda_bf16.h>

// Sinkhorn on 48x48 grids with K = max(exp(-5*L1cost), 1e-8).
// exp(-5c) < 1e-8 iff c >= 4, so:
//   K@v        = sum_{|dr|+|dc|<=3} (e^{-5c} - 1e-8) v  +  1e-8 * sum(v)
//   (K*C)@v    = sum_{diamond} c*(e^{-5c} - 1e-8) v     +  1e-8 * (Arow(r)+Acol(c))
// where Arow/Acol come from separable cost-weighted row/col sums.
// One CTA per sample, everything resident in shared memory, per-sample
// early exit once the reference's freeze condition fires.

#define NPIX  2304
#define WID   48
#define PW    54        // padded width (3-halo each side)
#define PAD   3
#define NTHR  576       // 48 rows x 12 groups of 4 pixels
#define NWARPS 18
#define MAXIT 250
#define EPSF  1e-8f
#define TOL2  1e-10f    // (1e-5)^2

struct SinkSmem {
    float u[PW * PW];      // padded, zero halo
    float v[PW * PW];      // padded, zero halo
    float xs[NPIX];
    float ys[NPIX];
    float red[48];         // reduction scratch: [0..17], [20..37], results [40],[41]
    float rowsum[WID], colsum[WID], arow[WID], acol[WID];
};

__device__ __forceinline__ float warpSum(float v) {
#pragma unroll
    for (int o = 16; o > 0; o >>= 1) v += __shfl_down_sync(0xffffffffu, v, o);
    return v;
}

__device__ __forceinline__ float blockSum(float val, float* red) {
    int lane = threadIdx.x & 31, wid = threadIdx.x >> 5;
    val = warpSum(val);
    if (lane == 0) red[wid] = val;
    __syncthreads();
    if (wid == 0) {
        float t = (lane < NWARPS) ? red[lane] : 0.f;
        t = warpSum(t);
        if (lane == 0) red[40] = t;
    }
    __syncthreads();
    return red[40];
}

__device__ __forceinline__ void blockSum2(float a, float b, float* red,
                                          float& ra, float& rb) {
    int lane = threadIdx.x & 31, wid = threadIdx.x >> 5;
    a = warpSum(a);
    b = warpSum(b);
    if (lane == 0) { red[wid] = a; red[20 + wid] = b; }
    __syncthreads();
    if (wid == 0) {
        float ta = (lane < NWARPS) ? red[lane] : 0.f;
        float tb = (lane < NWARPS) ? red[20 + lane] : 0.f;
        ta = warpSum(ta);
        tb = warpSum(tb);
        if (lane == 0) { red[40] = ta; red[41] = tb; }
    }
    __syncthreads();
    ra = red[40];
    rb = red[41];
}

// 25-tap L1-diamond (radius 3) stencil over a zero-haloed 54x54 image,
// 4 consecutive pixels per thread. Weight w[d] applied at |dr|+|dc| = d.
__device__ __forceinline__ void stencil4(const float* __restrict__ sp, int pbase,
                                         float w0, float w1, float w2, float w3,
                                         float a[4]) {
    const float* b0 = sp + pbase;
    a[0] = a[1] = a[2] = a[3] = 0.f;
    {   // dr = +/-3 : single tap
        const float* rm = b0 - 3 * PW;
        const float* rp = b0 + 3 * PW;
#pragma unroll
        for (int k = 0; k < 4; k++) a[k] += w3 * (rm[k] + rp[k]);
    }
    {   // dr = +/-2 : taps dc in [-1,1]
        const float* rm = b0 - 2 * PW;
        const float* rp = b0 + 2 * PW;
#pragma unroll
        for (int k = 0; k < 4; k++) {
            a[k] += w2 * (rm[k] + rp[k])
                  + w3 * (rm[k - 1] + rm[k + 1] + rp[k - 1] + rp[k + 1]);
        }
    }
    {   // dr = +/-1 : taps dc in [-2,2]
        const float* rm = b0 - PW;
        const float* rp = b0 + PW;
#pragma unroll
        for (int k = 0; k < 4; k++) {
            a[k] += w1 * (rm[k] + rp[k])
                  + w2 * (rm[k - 1] + rm[k + 1] + rp[k - 1] + rp[k + 1])
                  + w3 * (rm[k - 2] + rm[k + 2] + rp[k - 2] + rp[k + 2]);
        }
    }
    {   // dr = 0 : taps dc in [-3,3]
#pragma unroll
        for (int k = 0; k < 4; k++) {
            a[k] += w0 * b0[k]
                  + w1 * (b0[k - 1] + b0[k + 1])
                  + w2 * (b0[k - 2] + b0[k + 2])
                  + w3 * (b0[k - 3] + b0[k + 3]);
        }
    }
}

__global__ __launch_bounds__(NTHR, 1)
void wasserstein_sinkhorn_kernel(const float* __restrict__ x,
                                 const float* __restrict__ y,
                                 float* __restrict__ out) {
    __shared__ SinkSmem s;
    const int t = threadIdx.x;
    const int b = blockIdx.x;
    const int r = t / 12;
    const int c0 = (t % 12) * 4;
    const int pbase = (r + PAD) * PW + (c0 + PAD);
    const int gbase = t * 4;          // == r*48 + c0

    // exp(-5d) constants (fp32)
    const float e1 = 6.7379469990854670e-03f;   // exp(-5)
    const float e2 = 4.5399929762484854e-05f;   // exp(-10)
    const float e3 = 3.0590232050182579e-07f;   // exp(-15)
    const float w0 = 1.0f - EPSF;
    const float w1 = e1 - EPSF;
    const float w2 = e2 - EPSF;
    const float w3 = e3 - EPSF;
    const float wc1 = 1.0f * (e1 - EPSF);       // d * (exp(-5d) - 1e-8)
    const float wc2 = 2.0f * (e2 - EPSF);
    const float wc3 = 3.0f * (e3 - EPSF);

    // zero padded arrays (halos must be 0)
    for (int i = t; i < PW * PW; i += NTHR) { s.u[i] = 0.f; s.v[i] = 0.f; }

    // load x,y (sample b), normalize to probability vectors
    const float4 xv = reinterpret_cast<const float4*>(x + (size_t)b * NPIX)[t];
    const float4 yv = reinterpret_cast<const float4*>(y + (size_t)b * NPIX)[t];
    float Sx, Sy;
    blockSum2(xv.x + xv.y + xv.z + xv.w, yv.x + yv.y + yv.z + yv.w, s.red, Sx, Sy);
    s.xs[gbase + 0] = xv.x / Sx;  s.xs[gbase + 1] = xv.y / Sx;
    s.xs[gbase + 2] = xv.z / Sx;  s.xs[gbase + 3] = xv.w / Sx;
    s.ys[gbase + 0] = yv.x / Sy;  s.ys[gbase + 1] = yv.y / Sy;
    s.ys[gbase + 2] = yv.z / Sy;  s.ys[gbase + 3] = yv.w / Sy;

    const float u0 = 1.0f / 2304.0f;
    s.u[pbase + 0] = u0; s.u[pbase + 1] = u0;
    s.u[pbase + 2] = u0; s.u[pbase + 3] = u0;
    float Su = blockSum(4.0f * u0, s.red);   // barrier also publishes xs/ys/u

    // ---- Sinkhorn loop (early exit once the reference would freeze u) ----
    for (int it = 0; it < MAXIT; ++it) {
        float a[4];
        // v = ys / (K @ u)
        stencil4(s.u, pbase, w0, w1, w2, w3, a);
        float es = EPSF * Su;
        float v0 = s.ys[gbase + 0] / (a[0] + es);
        float v1 = s.ys[gbase + 1] / (a[1] + es);
        float v2 = s.ys[gbase + 2] / (a[2] + es);
        float v3 = s.ys[gbase + 3] / (a[3] + es);
        s.v[pbase + 0] = v0; s.v[pbase + 1] = v1;
        s.v[pbase + 2] = v2; s.v[pbase + 3] = v3;
        float Sv = blockSum(v0 + v1 + v2 + v3, s.red);

        // u_new = xs / (K @ v); accumulate diff^2 and sum(u_new)
        stencil4(s.v, pbase, w0, w1, w2, w3, a);
        es = EPSF * Sv;
        float d2 = 0.f, su = 0.f;
#pragma unroll
        for (int k = 0; k < 4; k++) {
            float un = s.xs[gbase + k] / (a[k] + es);
            float uo = s.u[pbase + k];
            float d = uo - un;
            d2 += d * d;
            su += un;
            s.u[pbase + k] = un;
        }
        float diff2;
        blockSum2(d2, su, s.red, diff2, Su);
        if (it > 0 && diff2 < TOL2) break;   // uniform across block
    }

    // ---- final v = ys / (K @ u) ----
    {
        float a[4];
        stencil4(s.u, pbase, w0, w1, w2, w3, a);
        float es = EPSF * Su;
#pragma unroll
        for (int k = 0; k < 4; k++)
            s.v[pbase + k] = s.ys[gbase + k] / (a[k] + es);
    }
    __syncthreads();

    // row/col sums of v (for the separable 1e-8 * cost term)
    if (t < WID) {
        float srs = 0.f;
        const float* row = s.v + (t + PAD) * PW + PAD;
#pragma unroll
        for (int c = 0; c < WID; c++) srs += row[c];
        s.rowsum[t] = srs;
    } else if (t >= 64 && t < 64 + WID) {
        int c = t - 64;
        float scs = 0.f;
        const float* col = s.v + PAD * PW + (c + PAD);
        for (int rr = 0; rr < WID; rr++) scs += col[rr * PW];
        s.colsum[c] = scs;
    }
    __syncthreads();
    if (t < WID) {
        float sa = 0.f;
        for (int rr = 0; rr < WID; rr++)
            sa += fabsf((float)(t - rr)) * s.rowsum[rr];
        s.arow[t] = sa;
    } else if (t >= 64 && t < 64 + WID) {
        int c = t - 64;
        float sa = 0.f;
        for (int cc = 0; cc < WID; cc++)
            sa += fabsf((float)(c - cc)) * s.colsum[cc];
        s.acol[c] = sa;
    }
    __syncthreads();

    // dist = sum_i u_i * ((K*C) @ v)_i
    float a[4];
    stencil4(s.v, pbase, 0.f, wc1, wc2, wc3, a);
    float ld = 0.f;
#pragma unroll
    for (int k = 0; k < 4; k++) {
        float kc = a[k] + EPSF * (s.arow[r] + s.acol[c0 + k]);
        ld += s.u[pbase + k] * kc;
    }
    float dist = blockSum(ld, s.red);
    if (t == 0) out[b] = dist;
}

extern "C" void kernel_launch(void* const* d_in, const int* in_sizes, int n_in,
                              void* d_out, int out_size) {
    const float* x = (const float*)d_in[0];
    const float* y = (const float*)d_in[1];
    float* out = (float*)d_out;
    int B = in_sizes[0] / NPIX;   // 8
    wasserstein_sinkhorn_kernel<<<B, NTHR>>>(x, y, out);
}